// round 9
// baseline (speedup 1.0000x reference)
#include <cuda_runtime.h>
#include <cuda_bf16.h>
#include <cstdint>
#include <math.h>

#define B_ROWS 16384
#define HID    1024
#define NJOUT  256
#define NJ     64

// ---------------------------------------------------------------------------
// Scratch (__device__ globals; allocation-free rule)
// Activations: [B, 2048] bf16 -> cols 0..1023 = hi plane, 1024..2047 = lo plane
// Weights:     [N, 2048] bf16 (transposed, K-major), hi|lo planes
// ---------------------------------------------------------------------------
__device__ __nv_bfloat16 g_act0[B_ROWS * 2048];
__device__ __nv_bfloat16 g_act1[B_ROWS * 2048];
__device__ __nv_bfloat16 g_w2t[HID * 2048];
__device__ __nv_bfloat16 g_w3t[HID * 2048];
__device__ __nv_bfloat16 g_w4t[NJOUT * 2048];
__device__ float         g_joints[B_ROWS * NJOUT];

__device__ __forceinline__ uint32_t smem_u32(const void* p) {
    uint32_t a;
    asm("{ .reg .u64 t; cvta.to.shared.u64 t, %1; cvt.u32.u64 %0, t; }"
        : "=r"(a) : "l"(p));
    return a;
}

__device__ __forceinline__ uint32_t pack_bf2(float a, float b) {
    __nv_bfloat162 p;
    p.x = __float2bfloat16(a);
    p.y = __float2bfloat16(b);
    return *(uint32_t*)&p;
}

// ---------------------------------------------------------------------------
// Weight split+transpose (tiled, coalesced both ways):
// W[K,N] fp32 -> out[N, 2K] bf16 (hi plane | lo plane)
// ---------------------------------------------------------------------------
__global__ void wsplit_kernel(const float* __restrict__ W,
                              __nv_bfloat16* __restrict__ out, int K, int N)
{
    __shared__ float s[32][33];
    const int n0 = blockIdx.x * 32;
    const int k0 = blockIdx.y * 32;
    const int tx = threadIdx.x;        // 0..31
    const int ty = threadIdx.y;        // 0..7

    #pragma unroll
    for (int r = ty; r < 32; r += 8)
        s[r][tx] = W[(size_t)(k0 + r) * N + n0 + tx];
    __syncthreads();

    #pragma unroll
    for (int r = ty; r < 32; r += 8) {
        float v = s[tx][r];            // = W[k0+tx][n0+r]
        __nv_bfloat16 hi = __float2bfloat16(v);
        __nv_bfloat16 lo = __float2bfloat16(v - __bfloat162float(hi));
        size_t base = (size_t)(n0 + r) * 2048 + k0 + tx;
        out[base] = hi;
        out[base + 1024] = lo;
    }
}

// ---------------------------------------------------------------------------
// Layer 1: [B,3]@[3,1024]+b1, leaky -> split bf16 [B,2048]. 8 outputs/thread.
// ---------------------------------------------------------------------------
__global__ void layer1_kernel(const float* __restrict__ x,
                              const float* __restrict__ W1,
                              const float* __restrict__ b1,
                              __nv_bfloat16* __restrict__ out)
{
    int t = blockIdx.x * blockDim.x + threadIdx.x;    // B_ROWS*128
    int i = t >> 7;
    int j0 = (t & 127) << 3;

    float x0 = x[i * 3 + 0], x1 = x[i * 3 + 1], x2 = x[i * 3 + 2];

    float v[8];
    {
        float4 ba = *(const float4*)&b1[j0];
        float4 bb = *(const float4*)&b1[j0 + 4];
        v[0] = ba.x; v[1] = ba.y; v[2] = ba.z; v[3] = ba.w;
        v[4] = bb.x; v[5] = bb.y; v[6] = bb.z; v[7] = bb.w;
    }
    #pragma unroll
    for (int r = 0; r < 3; r++) {
        float xr = (r == 0) ? x0 : (r == 1) ? x1 : x2;
        float4 wa = *(const float4*)&W1[r * 1024 + j0];
        float4 wb = *(const float4*)&W1[r * 1024 + j0 + 4];
        v[0] = fmaf(xr, wa.x, v[0]); v[1] = fmaf(xr, wa.y, v[1]);
        v[2] = fmaf(xr, wa.z, v[2]); v[3] = fmaf(xr, wa.w, v[3]);
        v[4] = fmaf(xr, wb.x, v[4]); v[5] = fmaf(xr, wb.y, v[5]);
        v[6] = fmaf(xr, wb.z, v[6]); v[7] = fmaf(xr, wb.w, v[7]);
    }

    uint4 hp, lp;
    uint32_t* hw = (uint32_t*)&hp;
    uint32_t* lw = (uint32_t*)&lp;
    #pragma unroll
    for (int p = 0; p < 4; p++) {
        float a = v[2 * p], b = v[2 * p + 1];
        a = (a >= 0.0f) ? a : 0.01f * a;
        b = (b >= 0.0f) ? b : 0.01f * b;
        __nv_bfloat16 ha = __float2bfloat16(a);
        __nv_bfloat16 hb = __float2bfloat16(b);
        float la = a - __bfloat162float(ha);
        float lb = b - __bfloat162float(hb);
        __nv_bfloat162 hv; hv.x = ha; hv.y = hb;
        hw[p] = *(uint32_t*)&hv;
        lw[p] = pack_bf2(la, lb);
    }
    *(uint4*)(out + (size_t)i * 2048 + j0)        = hp;
    *(uint4*)(out + (size_t)i * 2048 + 1024 + j0) = lp;
}

// ---------------------------------------------------------------------------
// HMMA GEMM with fragment reuse across the 3 split products.
//   Per K-chunk (32): stage Ah, Al, Bh, Bl tiles (8KB each) together and
//   compute Ah*Bh + Al*Bh + Ah*Bl from registers (12 LDSM per 48 MMA).
//   CTA tile 128x128; 8 warps = 4(m) x 2(n); warp tile 32x64.
//   Rows are 64B; swizzle: chunk ^ ((row>>1)&3)  (conflict-free ldmatrix).
//   3-stage cp.async pipeline, 32 chunks.
// ---------------------------------------------------------------------------
#define NCHUNK 32
#define STAGE_BYTES 32768
#define SMEM_REQ (3 * STAGE_BYTES + 512)

template<int ACT, int OUT_SPLIT>
__global__ void __launch_bounds__(256, 2)
mma_gemm(const __nv_bfloat16* __restrict__ A2,
         const __nv_bfloat16* __restrict__ BT,
         const float* __restrict__ bias,
         void* __restrict__ outp)
{
    extern __shared__ char dsmem[];
    const uint32_t sraw = smem_u32(dsmem);
    const uint32_t S = (sraw + 127u) & ~127u;
    char* Sp = dsmem + (S - sraw);

    const int tid = threadIdx.x;
    const int lane = tid & 31;
    const int wid = tid >> 5;
    const int warp_m = wid & 3;     // 4 warp-rows of 32
    const int warp_n = wid >> 2;    // 2 warp-cols of 64
    const int rowBase = blockIdx.y * 128;
    const int colBase = blockIdx.x * 128;

    // loader mapping: 512 x 16B per tile; thread does 2 rows' worth per tile
    const int ldRow = tid >> 2;    // 0..63 (+64 second iter)
    const int ldS   = tid & 3;     // 16B chunk within 64B row

    float acc[2][8][4];
    #pragma unroll
    for (int i = 0; i < 2; i++)
        #pragma unroll
        for (int j = 0; j < 8; j++)
            #pragma unroll
            for (int r = 0; r < 4; r++) acc[i][j][r] = 0.0f;

    // stage layout: Ah +0, Al +8K, Bh +16K, Bl +24K
    auto load_chunk = [&](int kc, int slot) {
        const uint32_t base = S + slot * STAGE_BYTES;
        const int colH = kc * 32;          // hi plane
        const int colL = 1024 + kc * 32;   // lo plane
        #pragma unroll
        for (int it = 0; it < 2; it++) {
            int row = ldRow + it * 64;
            uint32_t soff = row * 64 + ((ldS ^ ((row >> 1) & 3)) * 16);
            const void* sa_h = A2 + (size_t)(rowBase + row) * 2048 + colH + ldS * 8;
            const void* sa_l = A2 + (size_t)(rowBase + row) * 2048 + colL + ldS * 8;
            const void* sb_h = BT + (size_t)(colBase + row) * 2048 + colH + ldS * 8;
            const void* sb_l = BT + (size_t)(colBase + row) * 2048 + colL + ldS * 8;
            asm volatile("cp.async.cg.shared.global [%0], [%1], 16;\n"
                         :: "r"(base + soff), "l"(sa_h));
            asm volatile("cp.async.cg.shared.global [%0], [%1], 16;\n"
                         :: "r"(base + 8192 + soff), "l"(sa_l));
            asm volatile("cp.async.cg.shared.global [%0], [%1], 16;\n"
                         :: "r"(base + 16384 + soff), "l"(sb_h));
            asm volatile("cp.async.cg.shared.global [%0], [%1], 16;\n"
                         :: "r"(base + 24576 + soff), "l"(sb_l));
        }
        asm volatile("cp.async.commit_group;\n");
    };

    load_chunk(0, 0);
    load_chunk(1, 1);

    // ldmatrix lane mapping
    const int aR = lane & 15;        // row within 16-row m-tile
    const int aH = lane >> 4;        // k half (16B chunk +0/+1)
    const int bR = lane & 7;
    const int bQ = lane >> 3;        // quad 0..3

    for (int c = 0; c < NCHUNK; c++) {
        const int slot = c % 3;
        if (c + 1 < NCHUNK)
            asm volatile("cp.async.wait_group 1;\n" ::: "memory");
        else
            asm volatile("cp.async.wait_group 0;\n" ::: "memory");
        __syncthreads();

        if (c + 2 < NCHUNK)
            load_chunk(c + 2, (c + 2) % 3);

        const uint32_t stg0 = S + slot * STAGE_BYTES;
        const uint32_t AhT = stg0;
        const uint32_t AlT = stg0 + 8192;
        const uint32_t BhT = stg0 + 16384;
        const uint32_t BlT = stg0 + 24576;

        #pragma unroll
        for (int ks = 0; ks < 2; ks++) {
            // B fragments: 8 n8-tiles, hi and lo
            uint32_t bh[8][2], bl[8][2];
            #pragma unroll
            for (int p = 0; p < 4; p++) {
                int nrow = warp_n * 64 + p * 16 + (bQ >> 1) * 8 + bR;
                int ch = ks * 2 + (bQ & 1);
                uint32_t soff = nrow * 64 + ((ch ^ ((nrow >> 1) & 3)) * 16);
                uint32_t x0, x1, x2, x3;
                asm volatile("ldmatrix.sync.aligned.m8n8.x4.shared.b16 "
                             "{%0,%1,%2,%3}, [%4];"
                             : "=r"(x0), "=r"(x1), "=r"(x2), "=r"(x3)
                             : "r"(BhT + soff));
                bh[p * 2 + 0][0] = x0; bh[p * 2 + 0][1] = x1;
                bh[p * 2 + 1][0] = x2; bh[p * 2 + 1][1] = x3;
                asm volatile("ldmatrix.sync.aligned.m8n8.x4.shared.b16 "
                             "{%0,%1,%2,%3}, [%4];"
                             : "=r"(x0), "=r"(x1), "=r"(x2), "=r"(x3)
                             : "r"(BlT + soff));
                bl[p * 2 + 0][0] = x0; bl[p * 2 + 0][1] = x1;
                bl[p * 2 + 1][0] = x2; bl[p * 2 + 1][1] = x3;
            }
            #pragma unroll
            for (int i = 0; i < 2; i++) {
                int arow = warp_m * 32 + i * 16 + aR;
                int ch = ks * 2 + aH;
                uint32_t soff = arow * 64 + ((ch ^ ((arow >> 1) & 3)) * 16);
                uint32_t ah0, ah1, ah2, ah3, al0, al1, al2, al3;
                asm volatile("ldmatrix.sync.aligned.m8n8.x4.shared.b16 "
                             "{%0,%1,%2,%3}, [%4];"
                             : "=r"(ah0), "=r"(ah1), "=r"(ah2), "=r"(ah3)
                             : "r"(AhT + soff));
                asm volatile("ldmatrix.sync.aligned.m8n8.x4.shared.b16 "
                             "{%0,%1,%2,%3}, [%4];"
                             : "=r"(al0), "=r"(al1), "=r"(al2), "=r"(al3)
                             : "r"(AlT + soff));
                #pragma unroll
                for (int j = 0; j < 8; j++)
                    asm volatile(
                        "mma.sync.aligned.m16n8k16.row.col.f32.bf16.bf16.f32 "
                        "{%0,%1,%2,%3}, {%4,%5,%6,%7}, {%8,%9}, {%0,%1,%2,%3};"
                        : "+f"(acc[i][j][0]), "+f"(acc[i][j][1]),
                          "+f"(acc[i][j][2]), "+f"(acc[i][j][3])
                        : "r"(ah0), "r"(ah1), "r"(ah2), "r"(ah3),
                          "r"(bh[j][0]), "r"(bh[j][1]));
                #pragma unroll
                for (int j = 0; j < 8; j++)
                    asm volatile(
                        "mma.sync.aligned.m16n8k16.row.col.f32.bf16.bf16.f32 "
                        "{%0,%1,%2,%3}, {%4,%5,%6,%7}, {%8,%9}, {%0,%1,%2,%3};"
                        : "+f"(acc[i][j][0]), "+f"(acc[i][j][1]),
                          "+f"(acc[i][j][2]), "+f"(acc[i][j][3])
                        : "r"(al0), "r"(al1), "r"(al2), "r"(al3),
                          "r"(bh[j][0]), "r"(bh[j][1]));
                #pragma unroll
                for (int j = 0; j < 8; j++)
                    asm volatile(
                        "mma.sync.aligned.m16n8k16.row.col.f32.bf16.bf16.f32 "
                        "{%0,%1,%2,%3}, {%4,%5,%6,%7}, {%8,%9}, {%0,%1,%2,%3};"
                        : "+f"(acc[i][j][0]), "+f"(acc[i][j][1]),
                          "+f"(acc[i][j][2]), "+f"(acc[i][j][3])
                        : "r"(ah0), "r"(ah1), "r"(ah2), "r"(ah3),
                          "r"(bl[j][0]), "r"(bl[j][1]));
            }
        }
    }
    __syncthreads();   // all warps done with smem before epilogue reuse

    // ---------------- epilogue: stage fp32 -> smem, then coalesced out ------
    float* stg = (float*)Sp;          // [128][132] = 67.6KB < 96KB
    const int g = lane >> 2, t = lane & 3;
    #pragma unroll
    for (int i = 0; i < 2; i++) {
        int r0 = warp_m * 32 + i * 16 + g;
        #pragma unroll
        for (int j = 0; j < 8; j++) {
            int cc = warp_n * 64 + j * 8 + t * 2;
            *(float2*)&stg[r0 * 132 + cc]       = make_float2(acc[i][j][0], acc[i][j][1]);
            *(float2*)&stg[(r0 + 8) * 132 + cc] = make_float2(acc[i][j][2], acc[i][j][3]);
        }
    }
    __syncthreads();

    if (OUT_SPLIT) {
        __nv_bfloat16* O = (__nv_bfloat16*)outp;
        for (int idx = tid; idx < 128 * 64; idx += 256) {
            int row = idx >> 6, cc = (idx & 63) * 2;
            float v0 = stg[row * 132 + cc]     + bias[colBase + cc];
            float v1 = stg[row * 132 + cc + 1] + bias[colBase + cc + 1];
            if (ACT == 0) {
                v0 = (v0 >= 0.0f) ? v0 : 0.01f * v0;
                v1 = (v1 >= 0.0f) ? v1 : 0.01f * v1;
            } else {
                v0 = tanhf(v0); v1 = tanhf(v1);
            }
            __nv_bfloat16 h0 = __float2bfloat16(v0);
            __nv_bfloat16 h1 = __float2bfloat16(v1);
            float l0 = v0 - __bfloat162float(h0);
            float l1 = v1 - __bfloat162float(h1);
            size_t base = (size_t)(rowBase + row) * 2048 + colBase + cc;
            __nv_bfloat162 hv; hv.x = h0; hv.y = h1;
            *(uint32_t*)(O + base)        = *(uint32_t*)&hv;
            *(uint32_t*)(O + base + 1024) = pack_bf2(l0, l1);
        }
    } else {
        float* O = (float*)outp;
        for (int idx = tid; idx < 128 * 128; idx += 256) {
            int row = idx >> 7, cc = idx & 127;
            float v = stg[row * 132 + cc] + bias[colBase + cc];
            if (ACT == 0) v = (v >= 0.0f) ? v : 0.01f * v;
            else          v = tanhf(v);
            O[(size_t)(rowBase + row) * 256 + colBase + cc] = v;
        }
    }
}

// ---------------------------------------------------------------------------
// FK chain: one thread per row. Bottom homogeneous row stays (0,0,0,1),
// fp32(1 + 1e-9) == 1, so the final divide is identity.
// ---------------------------------------------------------------------------
__global__ void fk_kernel(const float* __restrict__ joints,
                          float* __restrict__ out)
{
    int row = blockIdx.x * blockDim.x + threadIdx.x;
    if (row >= B_ROWS) return;

    const float* q = joints + (size_t)row * NJOUT;
    float* o = out + (size_t)row * (NJ * 3);

    float M00 = 1, M01 = 0, M02 = 0;
    float M10 = 0, M11 = 1, M12 = 0;
    float M20 = 0, M21 = 0, M22 = 1;
    float px = 0, py = 0, pz = 0;

    for (int j = 0; j < NJ; j++) {
        float4 qv = *(const float4*)(q + 4 * j);
        float w = qv.x, x = qv.y, y = qv.z, z = qv.w;
        float s = 2.0f / (w * w + x * x + y * y + z * z);

        float r00 = 1.0f - s * (y * y + z * z);
        float r01 = s * (x * y - z * w);
        float r02 = s * (x * z + y * w);
        float r10 = s * (x * y + z * w);
        float r11 = 1.0f - s * (x * x + z * z);
        float r12 = s * (y * z - x * w);
        float r20 = s * (x * z - y * w);
        float r21 = s * (y * z + x * w);
        float r22 = 1.0f - s * (x * x + y * y);

        float tx = M00 * r01 + M01 * r11 + M02 * r21 + px;
        float ty = M10 * r01 + M11 * r11 + M12 * r21 + py;
        float tz = M20 * r01 + M21 * r11 + M22 * r21 + pz;

        float n00 = M00 * r00 + M01 * r10 + M02 * r20;
        float n01 = M00 * r01 + M01 * r11 + M02 * r21;
        float n02 = M00 * r02 + M01 * r12 + M02 * r22;
        float n10 = M10 * r00 + M11 * r10 + M12 * r20;
        float n11 = M10 * r01 + M11 * r11 + M12 * r21;
        float n12 = M10 * r02 + M11 * r12 + M12 * r22;
        float n20 = M20 * r00 + M21 * r10 + M22 * r20;
        float n21 = M20 * r01 + M21 * r11 + M22 * r21;
        float n22 = M20 * r02 + M21 * r12 + M22 * r22;

        M00 = n00; M01 = n01; M02 = n02;
        M10 = n10; M11 = n11; M12 = n12;
        M20 = n20; M21 = n21; M22 = n22;
        px = tx; py = ty; pz = tz;

        o[3 * j + 0] = px;
        o[3 * j + 1] = py;
        o[3 * j + 2] = pz;
    }
}

// ---------------------------------------------------------------------------
extern "C" void kernel_launch(void* const* d_in, const int* in_sizes, int n_in,
                              void* d_out, int out_size)
{
    const float* x  = (const float*)d_in[0];
    const float* W1 = (const float*)d_in[1];
    const float* b1 = (const float*)d_in[2];
    const float* W2 = (const float*)d_in[3];
    const float* b2 = (const float*)d_in[4];
    const float* W3 = (const float*)d_in[5];
    const float* b3 = (const float*)d_in[6];
    const float* W4 = (const float*)d_in[7];
    const float* b4 = (const float*)d_in[8];
    float* out = (float*)d_out;

    void *p_a0, *p_a1, *p_w2, *p_w3, *p_w4, *p_jt;
    cudaGetSymbolAddress(&p_a0, g_act0);
    cudaGetSymbolAddress(&p_a1, g_act1);
    cudaGetSymbolAddress(&p_w2, g_w2t);
    cudaGetSymbolAddress(&p_w3, g_w3t);
    cudaGetSymbolAddress(&p_w4, g_w4t);
    cudaGetSymbolAddress(&p_jt, g_joints);
    __nv_bfloat16* a0  = (__nv_bfloat16*)p_a0;
    __nv_bfloat16* a1  = (__nv_bfloat16*)p_a1;
    __nv_bfloat16* w2t = (__nv_bfloat16*)p_w2;
    __nv_bfloat16* w3t = (__nv_bfloat16*)p_w3;
    __nv_bfloat16* w4t = (__nv_bfloat16*)p_w4;
    float* jt = (float*)p_jt;

    cudaFuncSetAttribute(mma_gemm<0, 1>, cudaFuncAttributeMaxDynamicSharedMemorySize, SMEM_REQ);
    cudaFuncSetAttribute(mma_gemm<1, 0>, cudaFuncAttributeMaxDynamicSharedMemorySize, SMEM_REQ);

    // Weight split+transpose (tiled, coalesced)
    {
        dim3 blk(32, 8);
        wsplit_kernel<<<dim3(HID / 32, HID / 32), blk>>>(W2, w2t, HID, HID);
        wsplit_kernel<<<dim3(HID / 32, HID / 32), blk>>>(W3, w3t, HID, HID);
        wsplit_kernel<<<dim3(NJOUT / 32, HID / 32), blk>>>(W4, w4t, HID, NJOUT);
    }

    // Layer 1 (fp32, K=3) -> split act, 8 outputs per thread
    layer1_kernel<<<(B_ROWS * 128) / 256, 256>>>(x, W1, b1, a0);

    // Layers 2-4 on HMMA tensor cores
    {
        dim3 grid(HID / 128, B_ROWS / 128);
        mma_gemm<0, 1><<<grid, 256, SMEM_REQ>>>(a0, w2t, b2, a1);
        mma_gemm<0, 1><<<grid, 256, SMEM_REQ>>>(a1, w3t, b3, a0);
    }
    {
        dim3 grid(NJOUT / 128, B_ROWS / 128);
        mma_gemm<1, 0><<<grid, 256, SMEM_REQ>>>(a0, w4t, b4, jt);
    }

    // FK chain
    fk_kernel<<<B_ROWS / 128, 128>>>(jt, out);
}

// round 13
// speedup vs baseline: 1.5534x; 1.5534x over previous
#include <cuda_runtime.h>
#include <cuda_bf16.h>
#include <cstdint>
#include <math.h>

#define B_ROWS 16384
#define HID    1024
#define NJOUT  256
#define NJ     64

// ---------------------------------------------------------------------------
// Scratch (__device__ globals; allocation-free rule)
// Activations: [B, 2048] bf16 -> cols 0..1023 = hi plane, 1024..2047 = lo plane
// Weights:     [N, 2048] bf16 (transposed, K-major), hi|lo planes
// ---------------------------------------------------------------------------
__device__ __nv_bfloat16 g_act0[B_ROWS * 2048];
__device__ __nv_bfloat16 g_act1[B_ROWS * 2048];
__device__ __nv_bfloat16 g_w2t[HID * 2048];
__device__ __nv_bfloat16 g_w3t[HID * 2048];
__device__ __nv_bfloat16 g_w4t[NJOUT * 2048];
__device__ float         g_joints[B_ROWS * NJOUT];

__device__ __forceinline__ uint32_t smem_u32(const void* p) {
    uint32_t a;
    asm("{ .reg .u64 t; cvta.to.shared.u64 t, %1; cvt.u32.u64 %0, t; }"
        : "=r"(a) : "l"(p));
    return a;
}

__device__ __forceinline__ uint32_t pack_bf2(float a, float b) {
    __nv_bfloat162 p;
    p.x = __float2bfloat16(a);
    p.y = __float2bfloat16(b);
    return *(uint32_t*)&p;
}

// ---------------------------------------------------------------------------
// Weight split+transpose (tiled, coalesced both ways):
// W[K,N] fp32 -> out[N, 2K] bf16 (hi plane | lo plane)
// ---------------------------------------------------------------------------
__global__ void wsplit_kernel(const float* __restrict__ W,
                              __nv_bfloat16* __restrict__ out, int K, int N)
{
    __shared__ float s[32][33];
    const int n0 = blockIdx.x * 32;
    const int k0 = blockIdx.y * 32;
    const int tx = threadIdx.x;        // 0..31
    const int ty = threadIdx.y;        // 0..7

    #pragma unroll
    for (int r = ty; r < 32; r += 8)
        s[r][tx] = W[(size_t)(k0 + r) * N + n0 + tx];
    __syncthreads();

    #pragma unroll
    for (int r = ty; r < 32; r += 8) {
        float v = s[tx][r];            // = W[k0+tx][n0+r]
        __nv_bfloat16 hi = __float2bfloat16(v);
        __nv_bfloat16 lo = __float2bfloat16(v - __bfloat162float(hi));
        size_t base = (size_t)(n0 + r) * 2048 + k0 + tx;
        out[base] = hi;
        out[base + 1024] = lo;
    }
}

// ---------------------------------------------------------------------------
// Layer 1: [B,3]@[3,1024]+b1, leaky -> split bf16 [B,2048]. 8 outputs/thread.
// ---------------------------------------------------------------------------
__global__ void layer1_kernel(const float* __restrict__ x,
                              const float* __restrict__ W1,
                              const float* __restrict__ b1,
                              __nv_bfloat16* __restrict__ out)
{
    int t = blockIdx.x * blockDim.x + threadIdx.x;    // B_ROWS*128
    int i = t >> 7;
    int j0 = (t & 127) << 3;

    float x0 = x[i * 3 + 0], x1 = x[i * 3 + 1], x2 = x[i * 3 + 2];

    float v[8];
    {
        float4 ba = *(const float4*)&b1[j0];
        float4 bb = *(const float4*)&b1[j0 + 4];
        v[0] = ba.x; v[1] = ba.y; v[2] = ba.z; v[3] = ba.w;
        v[4] = bb.x; v[5] = bb.y; v[6] = bb.z; v[7] = bb.w;
    }
    #pragma unroll
    for (int r = 0; r < 3; r++) {
        float xr = (r == 0) ? x0 : (r == 1) ? x1 : x2;
        float4 wa = *(const float4*)&W1[r * 1024 + j0];
        float4 wb = *(const float4*)&W1[r * 1024 + j0 + 4];
        v[0] = fmaf(xr, wa.x, v[0]); v[1] = fmaf(xr, wa.y, v[1]);
        v[2] = fmaf(xr, wa.z, v[2]); v[3] = fmaf(xr, wa.w, v[3]);
        v[4] = fmaf(xr, wb.x, v[4]); v[5] = fmaf(xr, wb.y, v[5]);
        v[6] = fmaf(xr, wb.z, v[6]); v[7] = fmaf(xr, wb.w, v[7]);
    }

    uint4 hp, lp;
    uint32_t* hw = (uint32_t*)&hp;
    uint32_t* lw = (uint32_t*)&lp;
    #pragma unroll
    for (int p = 0; p < 4; p++) {
        float a = v[2 * p], b = v[2 * p + 1];
        a = (a >= 0.0f) ? a : 0.01f * a;
        b = (b >= 0.0f) ? b : 0.01f * b;
        __nv_bfloat16 ha = __float2bfloat16(a);
        __nv_bfloat16 hb = __float2bfloat16(b);
        float la = a - __bfloat162float(ha);
        float lb = b - __bfloat162float(hb);
        __nv_bfloat162 hv; hv.x = ha; hv.y = hb;
        hw[p] = *(uint32_t*)&hv;
        lw[p] = pack_bf2(la, lb);
    }
    *(uint4*)(out + (size_t)i * 2048 + j0)        = hp;
    *(uint4*)(out + (size_t)i * 2048 + 1024 + j0) = lp;
}

// ---------------------------------------------------------------------------
// HMMA GEMM with fragment reuse across the 3 split products.
//   Per K-chunk (32): stage Ah, Al, Bh, Bl tiles (8KB each); compute
//   Ah*Bh + Al*Bh + Ah*Bl. A fragments loaded once per ks (both i),
//   B streamed in 4 groups of 2 n-tiles to cap live registers (~95).
//   CTA tile 128x128; 8 warps = 4(m) x 2(n); warp tile 32x64.
//   Rows are 64B; swizzle: chunk ^ ((row>>1)&3)  (conflict-free ldmatrix).
//   3-stage cp.async pipeline, 32 chunks.
// ---------------------------------------------------------------------------
#define NCHUNK 32
#define STAGE_BYTES 32768
#define SMEM_REQ (3 * STAGE_BYTES + 512)

template<int ACT, int OUT_SPLIT>
__global__ void __launch_bounds__(256, 2)
mma_gemm(const __nv_bfloat16* __restrict__ A2,
         const __nv_bfloat16* __restrict__ BT,
         const float* __restrict__ bias,
         void* __restrict__ outp)
{
    extern __shared__ char dsmem[];
    const uint32_t sraw = smem_u32(dsmem);
    const uint32_t S = (sraw + 127u) & ~127u;
    char* Sp = dsmem + (S - sraw);

    const int tid = threadIdx.x;
    const int lane = tid & 31;
    const int wid = tid >> 5;
    const int warp_m = wid & 3;     // 4 warp-rows of 32
    const int warp_n = wid >> 2;    // 2 warp-cols of 64
    const int rowBase = blockIdx.y * 128;
    const int colBase = blockIdx.x * 128;

    // loader mapping: 512 x 16B per tile; thread does 2 rows' worth per tile
    const int ldRow = tid >> 2;    // 0..63 (+64 second iter)
    const int ldS   = tid & 3;     // 16B chunk within 64B row

    float acc[2][8][4];
    #pragma unroll
    for (int i = 0; i < 2; i++)
        #pragma unroll
        for (int j = 0; j < 8; j++)
            #pragma unroll
            for (int r = 0; r < 4; r++) acc[i][j][r] = 0.0f;

    // stage layout: Ah +0, Al +8K, Bh +16K, Bl +24K
    auto load_chunk = [&](int kc, int slot) {
        const uint32_t base = S + slot * STAGE_BYTES;
        const int colH = kc * 32;          // hi plane
        const int colL = 1024 + kc * 32;   // lo plane
        #pragma unroll
        for (int it = 0; it < 2; it++) {
            int row = ldRow + it * 64;
            uint32_t soff = row * 64 + ((ldS ^ ((row >> 1) & 3)) * 16);
            const void* sa_h = A2 + (size_t)(rowBase + row) * 2048 + colH + ldS * 8;
            const void* sa_l = A2 + (size_t)(rowBase + row) * 2048 + colL + ldS * 8;
            const void* sb_h = BT + (size_t)(colBase + row) * 2048 + colH + ldS * 8;
            const void* sb_l = BT + (size_t)(colBase + row) * 2048 + colL + ldS * 8;
            asm volatile("cp.async.cg.shared.global [%0], [%1], 16;\n"
                         :: "r"(base + soff), "l"(sa_h));
            asm volatile("cp.async.cg.shared.global [%0], [%1], 16;\n"
                         :: "r"(base + 8192 + soff), "l"(sa_l));
            asm volatile("cp.async.cg.shared.global [%0], [%1], 16;\n"
                         :: "r"(base + 16384 + soff), "l"(sb_h));
            asm volatile("cp.async.cg.shared.global [%0], [%1], 16;\n"
                         :: "r"(base + 24576 + soff), "l"(sb_l));
        }
        asm volatile("cp.async.commit_group;\n");
    };

    load_chunk(0, 0);
    load_chunk(1, 1);

    // ldmatrix lane mapping
    const int aR = lane & 15;        // row within 16-row m-tile
    const int aH = lane >> 4;        // k half (16B chunk +0/+1)
    const int bR = lane & 7;
    const int bQ = lane >> 3;        // quad 0..3

    for (int c = 0; c < NCHUNK; c++) {
        const int slot = c % 3;
        if (c + 1 < NCHUNK)
            asm volatile("cp.async.wait_group 1;\n" ::: "memory");
        else
            asm volatile("cp.async.wait_group 0;\n" ::: "memory");
        __syncthreads();

        if (c + 2 < NCHUNK)
            load_chunk(c + 2, (c + 2) % 3);

        const uint32_t stg0 = S + slot * STAGE_BYTES;
        const uint32_t AhT = stg0;
        const uint32_t AlT = stg0 + 8192;
        const uint32_t BhT = stg0 + 16384;
        const uint32_t BlT = stg0 + 24576;

        #pragma unroll
        for (int ks = 0; ks < 2; ks++) {
            // A fragments for both m-tiles, hi and lo (4 LDSM, 16 regs)
            uint32_t ah[2][4], al[2][4];
            #pragma unroll
            for (int i = 0; i < 2; i++) {
                int arow = warp_m * 32 + i * 16 + aR;
                int ch = ks * 2 + aH;
                uint32_t soff = arow * 64 + ((ch ^ ((arow >> 1) & 3)) * 16);
                asm volatile("ldmatrix.sync.aligned.m8n8.x4.shared.b16 "
                             "{%0,%1,%2,%3}, [%4];"
                             : "=r"(ah[i][0]), "=r"(ah[i][1]),
                               "=r"(ah[i][2]), "=r"(ah[i][3])
                             : "r"(AhT + soff));
                asm volatile("ldmatrix.sync.aligned.m8n8.x4.shared.b16 "
                             "{%0,%1,%2,%3}, [%4];"
                             : "=r"(al[i][0]), "=r"(al[i][1]),
                               "=r"(al[i][2]), "=r"(al[i][3])
                             : "r"(AlT + soff));
            }
            // B streamed in 4 groups of 2 n-tiles (8 live B regs)
            #pragma unroll
            for (int p = 0; p < 4; p++) {
                int nrow = warp_n * 64 + p * 16 + (bQ >> 1) * 8 + bR;
                int ch = ks * 2 + (bQ & 1);
                uint32_t soff = nrow * 64 + ((ch ^ ((nrow >> 1) & 3)) * 16);
                uint32_t bh[2][2], bl[2][2];
                asm volatile("ldmatrix.sync.aligned.m8n8.x4.shared.b16 "
                             "{%0,%1,%2,%3}, [%4];"
                             : "=r"(bh[0][0]), "=r"(bh[0][1]),
                               "=r"(bh[1][0]), "=r"(bh[1][1])
                             : "r"(BhT + soff));
                asm volatile("ldmatrix.sync.aligned.m8n8.x4.shared.b16 "
                             "{%0,%1,%2,%3}, [%4];"
                             : "=r"(bl[0][0]), "=r"(bl[0][1]),
                               "=r"(bl[1][0]), "=r"(bl[1][1])
                             : "r"(BlT + soff));
                #pragma unroll
                for (int i = 0; i < 2; i++) {
                    #pragma unroll
                    for (int jj = 0; jj < 2; jj++) {
                        const int j = p * 2 + jj;
                        asm volatile(
                            "mma.sync.aligned.m16n8k16.row.col.f32.bf16.bf16.f32 "
                            "{%0,%1,%2,%3}, {%4,%5,%6,%7}, {%8,%9}, {%0,%1,%2,%3};"
                            : "+f"(acc[i][j][0]), "+f"(acc[i][j][1]),
                              "+f"(acc[i][j][2]), "+f"(acc[i][j][3])
                            : "r"(ah[i][0]), "r"(ah[i][1]), "r"(ah[i][2]), "r"(ah[i][3]),
                              "r"(bh[jj][0]), "r"(bh[jj][1]));
                        asm volatile(
                            "mma.sync.aligned.m16n8k16.row.col.f32.bf16.bf16.f32 "
                            "{%0,%1,%2,%3}, {%4,%5,%6,%7}, {%8,%9}, {%0,%1,%2,%3};"
                            : "+f"(acc[i][j][0]), "+f"(acc[i][j][1]),
                              "+f"(acc[i][j][2]), "+f"(acc[i][j][3])
                            : "r"(al[i][0]), "r"(al[i][1]), "r"(al[i][2]), "r"(al[i][3]),
                              "r"(bh[jj][0]), "r"(bh[jj][1]));
                        asm volatile(
                            "mma.sync.aligned.m16n8k16.row.col.f32.bf16.bf16.f32 "
                            "{%0,%1,%2,%3}, {%4,%5,%6,%7}, {%8,%9}, {%0,%1,%2,%3};"
                            : "+f"(acc[i][j][0]), "+f"(acc[i][j][1]),
                              "+f"(acc[i][j][2]), "+f"(acc[i][j][3])
                            : "r"(ah[i][0]), "r"(ah[i][1]), "r"(ah[i][2]), "r"(ah[i][3]),
                              "r"(bl[jj][0]), "r"(bl[jj][1]));
                    }
                }
            }
        }
    }
    __syncthreads();   // all warps done with smem before epilogue reuse

    // ---------------- epilogue: stage fp32 -> smem, then coalesced out ------
    float* stg = (float*)Sp;          // [128][132] = 67.6KB < 96KB
    const int g = lane >> 2, t = lane & 3;
    #pragma unroll
    for (int i = 0; i < 2; i++) {
        int r0 = warp_m * 32 + i * 16 + g;
        #pragma unroll
        for (int j = 0; j < 8; j++) {
            int cc = warp_n * 64 + j * 8 + t * 2;
            *(float2*)&stg[r0 * 132 + cc]       = make_float2(acc[i][j][0], acc[i][j][1]);
            *(float2*)&stg[(r0 + 8) * 132 + cc] = make_float2(acc[i][j][2], acc[i][j][3]);
        }
    }
    __syncthreads();

    if (OUT_SPLIT) {
        __nv_bfloat16* O = (__nv_bfloat16*)outp;
        for (int idx = tid; idx < 128 * 64; idx += 256) {
            int row = idx >> 6, cc = (idx & 63) * 2;
            float v0 = stg[row * 132 + cc]     + bias[colBase + cc];
            float v1 = stg[row * 132 + cc + 1] + bias[colBase + cc + 1];
            if (ACT == 0) {
                v0 = (v0 >= 0.0f) ? v0 : 0.01f * v0;
                v1 = (v1 >= 0.0f) ? v1 : 0.01f * v1;
            } else {
                v0 = tanhf(v0); v1 = tanhf(v1);
            }
            __nv_bfloat16 h0 = __float2bfloat16(v0);
            __nv_bfloat16 h1 = __float2bfloat16(v1);
            float l0 = v0 - __bfloat162float(h0);
            float l1 = v1 - __bfloat162float(h1);
            size_t base = (size_t)(rowBase + row) * 2048 + colBase + cc;
            __nv_bfloat162 hv; hv.x = h0; hv.y = h1;
            *(uint32_t*)(O + base)        = *(uint32_t*)&hv;
            *(uint32_t*)(O + base + 1024) = pack_bf2(l0, l1);
        }
    } else {
        float* O = (float*)outp;
        for (int idx = tid; idx < 128 * 128; idx += 256) {
            int row = idx >> 7, cc = idx & 127;
            float v = stg[row * 132 + cc] + bias[colBase + cc];
            if (ACT == 0) v = (v >= 0.0f) ? v : 0.01f * v;
            else          v = tanhf(v);
            O[(size_t)(rowBase + row) * 256 + colBase + cc] = v;
        }
    }
}

// ---------------------------------------------------------------------------
// FK chain: one thread per row. Bottom homogeneous row stays (0,0,0,1),
// fp32(1 + 1e-9) == 1, so the final divide is identity.
// ---------------------------------------------------------------------------
__global__ void fk_kernel(const float* __restrict__ joints,
                          float* __restrict__ out)
{
    int row = blockIdx.x * blockDim.x + threadIdx.x;
    if (row >= B_ROWS) return;

    const float* q = joints + (size_t)row * NJOUT;
    float* o = out + (size_t)row * (NJ * 3);

    float M00 = 1, M01 = 0, M02 = 0;
    float M10 = 0, M11 = 1, M12 = 0;
    float M20 = 0, M21 = 0, M22 = 1;
    float px = 0, py = 0, pz = 0;

    for (int j = 0; j < NJ; j++) {
        float4 qv = *(const float4*)(q + 4 * j);
        float w = qv.x, x = qv.y, y = qv.z, z = qv.w;
        float s = 2.0f / (w * w + x * x + y * y + z * z);

        float r00 = 1.0f - s * (y * y + z * z);
        float r01 = s * (x * y - z * w);
        float r02 = s * (x * z + y * w);
        float r10 = s * (x * y + z * w);
        float r11 = 1.0f - s * (x * x + z * z);
        float r12 = s * (y * z - x * w);
        float r20 = s * (x * z - y * w);
        float r21 = s * (y * z + x * w);
        float r22 = 1.0f - s * (x * x + y * y);

        float tx = M00 * r01 + M01 * r11 + M02 * r21 + px;
        float ty = M10 * r01 + M11 * r11 + M12 * r21 + py;
        float tz = M20 * r01 + M21 * r11 + M22 * r21 + pz;

        float n00 = M00 * r00 + M01 * r10 + M02 * r20;
        float n01 = M00 * r01 + M01 * r11 + M02 * r21;
        float n02 = M00 * r02 + M01 * r12 + M02 * r22;
        float n10 = M10 * r00 + M11 * r10 + M12 * r20;
        float n11 = M10 * r01 + M11 * r11 + M12 * r21;
        float n12 = M10 * r02 + M11 * r12 + M12 * r22;
        float n20 = M20 * r00 + M21 * r10 + M22 * r20;
        float n21 = M20 * r01 + M21 * r11 + M22 * r21;
        float n22 = M20 * r02 + M21 * r12 + M22 * r22;

        M00 = n00; M01 = n01; M02 = n02;
        M10 = n10; M11 = n11; M12 = n12;
        M20 = n20; M21 = n21; M22 = n22;
        px = tx; py = ty; pz = tz;

        o[3 * j + 0] = px;
        o[3 * j + 1] = py;
        o[3 * j + 2] = pz;
    }
}

// ---------------------------------------------------------------------------
extern "C" void kernel_launch(void* const* d_in, const int* in_sizes, int n_in,
                              void* d_out, int out_size)
{
    const float* x  = (const float*)d_in[0];
    const float* W1 = (const float*)d_in[1];
    const float* b1 = (const float*)d_in[2];
    const float* W2 = (const float*)d_in[3];
    const float* b2 = (const float*)d_in[4];
    const float* W3 = (const float*)d_in[5];
    const float* b3 = (const float*)d_in[6];
    const float* W4 = (const float*)d_in[7];
    const float* b4 = (const float*)d_in[8];
    float* out = (float*)d_out;

    void *p_a0, *p_a1, *p_w2, *p_w3, *p_w4, *p_jt;
    cudaGetSymbolAddress(&p_a0, g_act0);
    cudaGetSymbolAddress(&p_a1, g_act1);
    cudaGetSymbolAddress(&p_w2, g_w2t);
    cudaGetSymbolAddress(&p_w3, g_w3t);
    cudaGetSymbolAddress(&p_w4, g_w4t);
    cudaGetSymbolAddress(&p_jt, g_joints);
    __nv_bfloat16* a0  = (__nv_bfloat16*)p_a0;
    __nv_bfloat16* a1  = (__nv_bfloat16*)p_a1;
    __nv_bfloat16* w2t = (__nv_bfloat16*)p_w2;
    __nv_bfloat16* w3t = (__nv_bfloat16*)p_w3;
    __nv_bfloat16* w4t = (__nv_bfloat16*)p_w4;
    float* jt = (float*)p_jt;

    cudaFuncSetAttribute(mma_gemm<0, 1>, cudaFuncAttributeMaxDynamicSharedMemorySize, SMEM_REQ);
    cudaFuncSetAttribute(mma_gemm<1, 0>, cudaFuncAttributeMaxDynamicSharedMemorySize, SMEM_REQ);

    // Weight split+transpose (tiled, coalesced)
    {
        dim3 blk(32, 8);
        wsplit_kernel<<<dim3(HID / 32, HID / 32), blk>>>(W2, w2t, HID, HID);
        wsplit_kernel<<<dim3(HID / 32, HID / 32), blk>>>(W3, w3t, HID, HID);
        wsplit_kernel<<<dim3(NJOUT / 32, HID / 32), blk>>>(W4, w4t, HID, NJOUT);
    }

    // Layer 1 (fp32, K=3) -> split act, 8 outputs per thread
    layer1_kernel<<<(B_ROWS * 128) / 256, 256>>>(x, W1, b1, a0);

    // Layers 2-4 on HMMA tensor cores
    {
        dim3 grid(HID / 128, B_ROWS / 128);
        mma_gemm<0, 1><<<grid, 256, SMEM_REQ>>>(a0, w2t, b2, a1);
        mma_gemm<0, 1><<<grid, 256, SMEM_REQ>>>(a1, w3t, b3, a0);
    }
    {
        dim3 grid(NJOUT / 128, B_ROWS / 128);
        mma_gemm<1, 0><<<grid, 256, SMEM_REQ>>>(a0, w4t, b4, jt);
    }

    // FK chain
    fk_kernel<<<B_ROWS / 128, 128>>>(jt, out);
}

// round 15
// speedup vs baseline: 1.5570x; 1.0023x over previous
#include <cuda_runtime.h>
#include <cuda_bf16.h>
#include <cstdint>
#include <math.h>

#define B_ROWS 16384
#define HID    1024
#define NJOUT  256
#define NJ     64

// ---------------------------------------------------------------------------
// Scratch (__device__ globals; allocation-free rule)
// Activations: [B, 2048] bf16 -> cols 0..1023 = hi plane, 1024..2047 = lo plane
// Weights:     [N, 2048] bf16 (transposed, K-major), hi|lo planes
// ---------------------------------------------------------------------------
__device__ __nv_bfloat16 g_act0[B_ROWS * 2048];
__device__ __nv_bfloat16 g_act1[B_ROWS * 2048];
__device__ __nv_bfloat16 g_w2t[HID * 2048];
__device__ __nv_bfloat16 g_w3t[HID * 2048];
__device__ __nv_bfloat16 g_w4t[NJOUT * 2048];
__device__ float         g_joints[B_ROWS * NJOUT];

__device__ __forceinline__ uint32_t smem_u32(const void* p) {
    uint32_t a;
    asm("{ .reg .u64 t; cvta.to.shared.u64 t, %1; cvt.u32.u64 %0, t; }"
        : "=r"(a) : "l"(p));
    return a;
}

__device__ __forceinline__ uint32_t pack_bf2(float a, float b) {
    __nv_bfloat162 p;
    p.x = __float2bfloat16(a);
    p.y = __float2bfloat16(b);
    return *(uint32_t*)&p;
}

// ---------------------------------------------------------------------------
// Weight split+transpose (tiled, coalesced both ways):
// W[K,N] fp32 -> out[N, 2K] bf16 (hi plane | lo plane)
// ---------------------------------------------------------------------------
__global__ void wsplit_kernel(const float* __restrict__ W,
                              __nv_bfloat16* __restrict__ out, int K, int N)
{
    __shared__ float s[32][33];
    const int n0 = blockIdx.x * 32;
    const int k0 = blockIdx.y * 32;
    const int tx = threadIdx.x;        // 0..31
    const int ty = threadIdx.y;        // 0..7

    #pragma unroll
    for (int r = ty; r < 32; r += 8)
        s[r][tx] = W[(size_t)(k0 + r) * N + n0 + tx];
    __syncthreads();

    #pragma unroll
    for (int r = ty; r < 32; r += 8) {
        float v = s[tx][r];            // = W[k0+tx][n0+r]
        __nv_bfloat16 hi = __float2bfloat16(v);
        __nv_bfloat16 lo = __float2bfloat16(v - __bfloat162float(hi));
        size_t base = (size_t)(n0 + r) * 2048 + k0 + tx;
        out[base] = hi;
        out[base + 1024] = lo;
    }
}

// ---------------------------------------------------------------------------
// Layer 1: [B,3]@[3,1024]+b1, leaky -> split bf16 [B,2048]. 8 outputs/thread.
// ---------------------------------------------------------------------------
__global__ void layer1_kernel(const float* __restrict__ x,
                              const float* __restrict__ W1,
                              const float* __restrict__ b1,
                              __nv_bfloat16* __restrict__ out)
{
    int t = blockIdx.x * blockDim.x + threadIdx.x;    // B_ROWS*128
    int i = t >> 7;
    int j0 = (t & 127) << 3;

    float x0 = x[i * 3 + 0], x1 = x[i * 3 + 1], x2 = x[i * 3 + 2];

    float v[8];
    {
        float4 ba = *(const float4*)&b1[j0];
        float4 bb = *(const float4*)&b1[j0 + 4];
        v[0] = ba.x; v[1] = ba.y; v[2] = ba.z; v[3] = ba.w;
        v[4] = bb.x; v[5] = bb.y; v[6] = bb.z; v[7] = bb.w;
    }
    #pragma unroll
    for (int r = 0; r < 3; r++) {
        float xr = (r == 0) ? x0 : (r == 1) ? x1 : x2;
        float4 wa = *(const float4*)&W1[r * 1024 + j0];
        float4 wb = *(const float4*)&W1[r * 1024 + j0 + 4];
        v[0] = fmaf(xr, wa.x, v[0]); v[1] = fmaf(xr, wa.y, v[1]);
        v[2] = fmaf(xr, wa.z, v[2]); v[3] = fmaf(xr, wa.w, v[3]);
        v[4] = fmaf(xr, wb.x, v[4]); v[5] = fmaf(xr, wb.y, v[5]);
        v[6] = fmaf(xr, wb.z, v[6]); v[7] = fmaf(xr, wb.w, v[7]);
    }

    uint4 hp, lp;
    uint32_t* hw = (uint32_t*)&hp;
    uint32_t* lw = (uint32_t*)&lp;
    #pragma unroll
    for (int p = 0; p < 4; p++) {
        float a = v[2 * p], b = v[2 * p + 1];
        a = (a >= 0.0f) ? a : 0.01f * a;
        b = (b >= 0.0f) ? b : 0.01f * b;
        __nv_bfloat16 ha = __float2bfloat16(a);
        __nv_bfloat16 hb = __float2bfloat16(b);
        float la = a - __bfloat162float(ha);
        float lb = b - __bfloat162float(hb);
        __nv_bfloat162 hv; hv.x = ha; hv.y = hb;
        hw[p] = *(uint32_t*)&hv;
        lw[p] = pack_bf2(la, lb);
    }
    *(uint4*)(out + (size_t)i * 2048 + j0)        = hp;
    *(uint4*)(out + (size_t)i * 2048 + 1024 + j0) = lp;
}

// ---------------------------------------------------------------------------
// HMMA GEMM with fragment reuse across the 3 split products.
//   Per K-chunk (32): stage Ah, Al, Bh, Bl tiles (8KB each); compute
//   Ah*Bh + Al*Bh + Ah*Bl. A fragments loaded once per ks (both i),
//   B streamed in 4 groups of 2 n-tiles. MMAs grouped BY PRODUCT within
//   each p-group so same-accumulator chains are spaced by 4 indep MMAs.
//   CTA tile 128x128; 8 warps = 4(m) x 2(n); warp tile 32x64.
//   Rows are 64B; swizzle: chunk ^ ((row>>1)&3)  (conflict-free ldmatrix).
//   3-stage cp.async pipeline, 32 chunks.
// ---------------------------------------------------------------------------
#define NCHUNK 32
#define STAGE_BYTES 32768
#define SMEM_REQ (3 * STAGE_BYTES + 512)

template<int ACT, int OUT_SPLIT>
__global__ void __launch_bounds__(256, 2)
mma_gemm(const __nv_bfloat16* __restrict__ A2,
         const __nv_bfloat16* __restrict__ BT,
         const float* __restrict__ bias,
         void* __restrict__ outp)
{
    extern __shared__ char dsmem[];
    const uint32_t sraw = smem_u32(dsmem);
    const uint32_t S = (sraw + 127u) & ~127u;
    char* Sp = dsmem + (S - sraw);

    const int tid = threadIdx.x;
    const int lane = tid & 31;
    const int wid = tid >> 5;
    const int warp_m = wid & 3;     // 4 warp-rows of 32
    const int warp_n = wid >> 2;    // 2 warp-cols of 64
    const int rowBase = blockIdx.y * 128;
    const int colBase = blockIdx.x * 128;

    // loader mapping: 512 x 16B per tile; thread does 2 rows' worth per tile
    const int ldRow = tid >> 2;    // 0..63 (+64 second iter)
    const int ldS   = tid & 3;     // 16B chunk within 64B row

    float acc[2][8][4];
    #pragma unroll
    for (int i = 0; i < 2; i++)
        #pragma unroll
        for (int j = 0; j < 8; j++)
            #pragma unroll
            for (int r = 0; r < 4; r++) acc[i][j][r] = 0.0f;

    // stage layout: Ah +0, Al +8K, Bh +16K, Bl +24K
    auto load_chunk = [&](int kc, int slot) {
        const uint32_t base = S + slot * STAGE_BYTES;
        const int colH = kc * 32;          // hi plane
        const int colL = 1024 + kc * 32;   // lo plane
        #pragma unroll
        for (int it = 0; it < 2; it++) {
            int row = ldRow + it * 64;
            uint32_t soff = row * 64 + ((ldS ^ ((row >> 1) & 3)) * 16);
            const void* sa_h = A2 + (size_t)(rowBase + row) * 2048 + colH + ldS * 8;
            const void* sa_l = A2 + (size_t)(rowBase + row) * 2048 + colL + ldS * 8;
            const void* sb_h = BT + (size_t)(colBase + row) * 2048 + colH + ldS * 8;
            const void* sb_l = BT + (size_t)(colBase + row) * 2048 + colL + ldS * 8;
            asm volatile("cp.async.cg.shared.global [%0], [%1], 16;\n"
                         :: "r"(base + soff), "l"(sa_h));
            asm volatile("cp.async.cg.shared.global [%0], [%1], 16;\n"
                         :: "r"(base + 8192 + soff), "l"(sa_l));
            asm volatile("cp.async.cg.shared.global [%0], [%1], 16;\n"
                         :: "r"(base + 16384 + soff), "l"(sb_h));
            asm volatile("cp.async.cg.shared.global [%0], [%1], 16;\n"
                         :: "r"(base + 24576 + soff), "l"(sb_l));
        }
        asm volatile("cp.async.commit_group;\n");
    };

    load_chunk(0, 0);
    load_chunk(1, 1);

    // ldmatrix lane mapping
    const int aR = lane & 15;        // row within 16-row m-tile
    const int aH = lane >> 4;        // k half (16B chunk +0/+1)
    const int bR = lane & 7;
    const int bQ = lane >> 3;        // quad 0..3

    for (int c = 0; c < NCHUNK; c++) {
        const int slot = c % 3;
        if (c + 1 < NCHUNK)
            asm volatile("cp.async.wait_group 1;\n" ::: "memory");
        else
            asm volatile("cp.async.wait_group 0;\n" ::: "memory");
        __syncthreads();

        if (c + 2 < NCHUNK)
            load_chunk(c + 2, (c + 2) % 3);

        const uint32_t stg0 = S + slot * STAGE_BYTES;
        const uint32_t AhT = stg0;
        const uint32_t AlT = stg0 + 8192;
        const uint32_t BhT = stg0 + 16384;
        const uint32_t BlT = stg0 + 24576;

        #pragma unroll
        for (int ks = 0; ks < 2; ks++) {
            // A fragments for both m-tiles, hi and lo (4 LDSM, 16 regs)
            uint32_t ah[2][4], al[2][4];
            #pragma unroll
            for (int i = 0; i < 2; i++) {
                int arow = warp_m * 32 + i * 16 + aR;
                int ch = ks * 2 + aH;
                uint32_t soff = arow * 64 + ((ch ^ ((arow >> 1) & 3)) * 16);
                asm volatile("ldmatrix.sync.aligned.m8n8.x4.shared.b16 "
                             "{%0,%1,%2,%3}, [%4];"
                             : "=r"(ah[i][0]), "=r"(ah[i][1]),
                               "=r"(ah[i][2]), "=r"(ah[i][3])
                             : "r"(AhT + soff));
                asm volatile("ldmatrix.sync.aligned.m8n8.x4.shared.b16 "
                             "{%0,%1,%2,%3}, [%4];"
                             : "=r"(al[i][0]), "=r"(al[i][1]),
                               "=r"(al[i][2]), "=r"(al[i][3])
                             : "r"(AlT + soff));
            }
            // B streamed in 4 groups of 2 n-tiles (8 live B regs)
            #pragma unroll
            for (int p = 0; p < 4; p++) {
                int nrow = warp_n * 64 + p * 16 + (bQ >> 1) * 8 + bR;
                int ch = ks * 2 + (bQ & 1);
                uint32_t soff = nrow * 64 + ((ch ^ ((nrow >> 1) & 3)) * 16);
                uint32_t bh[2][2], bl[2][2];
                asm volatile("ldmatrix.sync.aligned.m8n8.x4.shared.b16 "
                             "{%0,%1,%2,%3}, [%4];"
                             : "=r"(bh[0][0]), "=r"(bh[0][1]),
                               "=r"(bh[1][0]), "=r"(bh[1][1])
                             : "r"(BhT + soff));
                asm volatile("ldmatrix.sync.aligned.m8n8.x4.shared.b16 "
                             "{%0,%1,%2,%3}, [%4];"
                             : "=r"(bl[0][0]), "=r"(bl[0][1]),
                               "=r"(bl[1][0]), "=r"(bl[1][1])
                             : "r"(BlT + soff));
                // Product-grouped issue: all hh, then all lh, then all hl.
                // Per-accumulator order stays hh -> lh -> hl (bitwise same),
                // but same-acc chain links are 4 independent MMAs apart.
                #pragma unroll
                for (int i = 0; i < 2; i++)
                    #pragma unroll
                    for (int jj = 0; jj < 2; jj++) {
                        const int j = p * 2 + jj;
                        asm volatile(
                            "mma.sync.aligned.m16n8k16.row.col.f32.bf16.bf16.f32 "
                            "{%0,%1,%2,%3}, {%4,%5,%6,%7}, {%8,%9}, {%0,%1,%2,%3};"
                            : "+f"(acc[i][j][0]), "+f"(acc[i][j][1]),
                              "+f"(acc[i][j][2]), "+f"(acc[i][j][3])
                            : "r"(ah[i][0]), "r"(ah[i][1]), "r"(ah[i][2]), "r"(ah[i][3]),
                              "r"(bh[jj][0]), "r"(bh[jj][1]));
                    }
                #pragma unroll
                for (int i = 0; i < 2; i++)
                    #pragma unroll
                    for (int jj = 0; jj < 2; jj++) {
                        const int j = p * 2 + jj;
                        asm volatile(
                            "mma.sync.aligned.m16n8k16.row.col.f32.bf16.bf16.f32 "
                            "{%0,%1,%2,%3}, {%4,%5,%6,%7}, {%8,%9}, {%0,%1,%2,%3};"
                            : "+f"(acc[i][j][0]), "+f"(acc[i][j][1]),
                              "+f"(acc[i][j][2]), "+f"(acc[i][j][3])
                            : "r"(al[i][0]), "r"(al[i][1]), "r"(al[i][2]), "r"(al[i][3]),
                              "r"(bh[jj][0]), "r"(bh[jj][1]));
                    }
                #pragma unroll
                for (int i = 0; i < 2; i++)
                    #pragma unroll
                    for (int jj = 0; jj < 2; jj++) {
                        const int j = p * 2 + jj;
                        asm volatile(
                            "mma.sync.aligned.m16n8k16.row.col.f32.bf16.bf16.f32 "
                            "{%0,%1,%2,%3}, {%4,%5,%6,%7}, {%8,%9}, {%0,%1,%2,%3};"
                            : "+f"(acc[i][j][0]), "+f"(acc[i][j][1]),
                              "+f"(acc[i][j][2]), "+f"(acc[i][j][3])
                            : "r"(ah[i][0]), "r"(ah[i][1]), "r"(ah[i][2]), "r"(ah[i][3]),
                              "r"(bl[jj][0]), "r"(bl[jj][1]));
                    }
            }
        }
    }
    __syncthreads();   // all warps done with smem before epilogue reuse

    // ---------------- epilogue: stage fp32 -> smem, then coalesced out ------
    float* stg = (float*)Sp;          // [128][132] = 67.6KB < 96KB
    const int g = lane >> 2, t = lane & 3;
    #pragma unroll
    for (int i = 0; i < 2; i++) {
        int r0 = warp_m * 32 + i * 16 + g;
        #pragma unroll
        for (int j = 0; j < 8; j++) {
            int cc = warp_n * 64 + j * 8 + t * 2;
            *(float2*)&stg[r0 * 132 + cc]       = make_float2(acc[i][j][0], acc[i][j][1]);
            *(float2*)&stg[(r0 + 8) * 132 + cc] = make_float2(acc[i][j][2], acc[i][j][3]);
        }
    }
    __syncthreads();

    if (OUT_SPLIT) {
        __nv_bfloat16* O = (__nv_bfloat16*)outp;
        for (int idx = tid; idx < 128 * 64; idx += 256) {
            int row = idx >> 6, cc = (idx & 63) * 2;
            float v0 = stg[row * 132 + cc]     + bias[colBase + cc];
            float v1 = stg[row * 132 + cc + 1] + bias[colBase + cc + 1];
            if (ACT == 0) {
                v0 = (v0 >= 0.0f) ? v0 : 0.01f * v0;
                v1 = (v1 >= 0.0f) ? v1 : 0.01f * v1;
            } else {
                v0 = tanhf(v0); v1 = tanhf(v1);
            }
            __nv_bfloat16 h0 = __float2bfloat16(v0);
            __nv_bfloat16 h1 = __float2bfloat16(v1);
            float l0 = v0 - __bfloat162float(h0);
            float l1 = v1 - __bfloat162float(h1);
            size_t base = (size_t)(rowBase + row) * 2048 + colBase + cc;
            __nv_bfloat162 hv; hv.x = h0; hv.y = h1;
            *(uint32_t*)(O + base)        = *(uint32_t*)&hv;
            *(uint32_t*)(O + base + 1024) = pack_bf2(l0, l1);
        }
    } else {
        float* O = (float*)outp;
        for (int idx = tid; idx < 128 * 128; idx += 256) {
            int row = idx >> 7, cc = idx & 127;
            float v = stg[row * 132 + cc] + bias[colBase + cc];
            if (ACT == 0) v = (v >= 0.0f) ? v : 0.01f * v;
            else          v = tanhf(v);
            O[(size_t)(rowBase + row) * 256 + colBase + cc] = v;
        }
    }
}

// ---------------------------------------------------------------------------
// FK chain: one thread per row. Bottom homogeneous row stays (0,0,0,1),
// fp32(1 + 1e-9) == 1, so the final divide is identity.
// ---------------------------------------------------------------------------
__global__ void fk_kernel(const float* __restrict__ joints,
                          float* __restrict__ out)
{
    int row = blockIdx.x * blockDim.x + threadIdx.x;
    if (row >= B_ROWS) return;

    const float* q = joints + (size_t)row * NJOUT;
    float* o = out + (size_t)row * (NJ * 3);

    float M00 = 1, M01 = 0, M02 = 0;
    float M10 = 0, M11 = 1, M12 = 0;
    float M20 = 0, M21 = 0, M22 = 1;
    float px = 0, py = 0, pz = 0;

    for (int j = 0; j < NJ; j++) {
        float4 qv = *(const float4*)(q + 4 * j);
        float w = qv.x, x = qv.y, y = qv.z, z = qv.w;
        float s = 2.0f / (w * w + x * x + y * y + z * z);

        float r00 = 1.0f - s * (y * y + z * z);
        float r01 = s * (x * y - z * w);
        float r02 = s * (x * z + y * w);
        float r10 = s * (x * y + z * w);
        float r11 = 1.0f - s * (x * x + z * z);
        float r12 = s * (y * z - x * w);
        float r20 = s * (x * z - y * w);
        float r21 = s * (y * z + x * w);
        float r22 = 1.0f - s * (x * x + y * y);

        float tx = M00 * r01 + M01 * r11 + M02 * r21 + px;
        float ty = M10 * r01 + M11 * r11 + M12 * r21 + py;
        float tz = M20 * r01 + M21 * r11 + M22 * r21 + pz;

        float n00 = M00 * r00 + M01 * r10 + M02 * r20;
        float n01 = M00 * r01 + M01 * r11 + M02 * r21;
        float n02 = M00 * r02 + M01 * r12 + M02 * r22;
        float n10 = M10 * r00 + M11 * r10 + M12 * r20;
        float n11 = M10 * r01 + M11 * r11 + M12 * r21;
        float n12 = M10 * r02 + M11 * r12 + M12 * r22;
        float n20 = M20 * r00 + M21 * r10 + M22 * r20;
        float n21 = M20 * r01 + M21 * r11 + M22 * r21;
        float n22 = M20 * r02 + M21 * r12 + M22 * r22;

        M00 = n00; M01 = n01; M02 = n02;
        M10 = n10; M11 = n11; M12 = n12;
        M20 = n20; M21 = n21; M22 = n22;
        px = tx; py = ty; pz = tz;

        o[3 * j + 0] = px;
        o[3 * j + 1] = py;
        o[3 * j + 2] = pz;
    }
}

// ---------------------------------------------------------------------------
extern "C" void kernel_launch(void* const* d_in, const int* in_sizes, int n_in,
                              void* d_out, int out_size)
{
    const float* x  = (const float*)d_in[0];
    const float* W1 = (const float*)d_in[1];
    const float* b1 = (const float*)d_in[2];
    const float* W2 = (const float*)d_in[3];
    const float* b2 = (const float*)d_in[4];
    const float* W3 = (const float*)d_in[5];
    const float* b3 = (const float*)d_in[6];
    const float* W4 = (const float*)d_in[7];
    const float* b4 = (const float*)d_in[8];
    float* out = (float*)d_out;

    void *p_a0, *p_a1, *p_w2, *p_w3, *p_w4, *p_jt;
    cudaGetSymbolAddress(&p_a0, g_act0);
    cudaGetSymbolAddress(&p_a1, g_act1);
    cudaGetSymbolAddress(&p_w2, g_w2t);
    cudaGetSymbolAddress(&p_w3, g_w3t);
    cudaGetSymbolAddress(&p_w4, g_w4t);
    cudaGetSymbolAddress(&p_jt, g_joints);
    __nv_bfloat16* a0  = (__nv_bfloat16*)p_a0;
    __nv_bfloat16* a1  = (__nv_bfloat16*)p_a1;
    __nv_bfloat16* w2t = (__nv_bfloat16*)p_w2;
    __nv_bfloat16* w3t = (__nv_bfloat16*)p_w3;
    __nv_bfloat16* w4t = (__nv_bfloat16*)p_w4;
    float* jt = (float*)p_jt;

    cudaFuncSetAttribute(mma_gemm<0, 1>, cudaFuncAttributeMaxDynamicSharedMemorySize, SMEM_REQ);
    cudaFuncSetAttribute(mma_gemm<1, 0>, cudaFuncAttributeMaxDynamicSharedMemorySize, SMEM_REQ);

    dim3 wblk(32, 8);

    // Launch order arranged so the 4th launch is mma_gemm (ncu capture slot).
    // Dependencies: L2 needs w2t + a0; L3 needs w3t + a1; L4 needs w4t.
    wsplit_kernel<<<dim3(HID / 32, HID / 32), wblk>>>(W2, w2t, HID, HID);       // 1
    layer1_kernel<<<(B_ROWS * 128) / 256, 256>>>(x, W1, b1, a0);                // 2
    wsplit_kernel<<<dim3(HID / 32, HID / 32), wblk>>>(W3, w3t, HID, HID);       // 3
    {
        dim3 grid(HID / 128, B_ROWS / 128);
        mma_gemm<0, 1><<<grid, 256, SMEM_REQ>>>(a0, w2t, b2, a1);               // 4 (L2)
    }
    wsplit_kernel<<<dim3(NJOUT / 32, HID / 32), wblk>>>(W4, w4t, HID, NJOUT);   // 5
    {
        dim3 grid(HID / 128, B_ROWS / 128);
        mma_gemm<0, 1><<<grid, 256, SMEM_REQ>>>(a1, w3t, b3, a0);               // 6 (L3)
    }
    {
        dim3 grid(NJOUT / 128, B_ROWS / 128);
        mma_gemm<1, 0><<<grid, 256, SMEM_REQ>>>(a0, w4t, b4, jt);               // 7 (L4)
    }
    fk_kernel<<<B_ROWS / 128, 128>>>(jt, out);                                  // 8
}